// round 4
// baseline (speedup 1.0000x reference)
#include <cuda_runtime.h>
#include <cuda_bf16.h>
#include <math_constants.h>

// AttentionMax: correlation[b,s] = <q[b], sub[b,s]>, argmax over s, one-hot out [bz, ns, 1]
// bz=4096, ns=256, d=128, fp32. Memory-bound: 512MB stream of feat_sub.
//
// R4: persistent grid (148*4 CTAs, batch-strided loop) to eliminate the 6 wave
// transitions + 4096 CTA prologues that diluted DRAM duty cycle to 86%.
// Inner loop = R3 (pipelined 4-row double buffer + multi-row shuffle reduce).

#define NS 256
#define D  128

__device__ __forceinline__ float reduce4(float p0, float p1, float p2, float p3,
                                         int lane)
{
    const unsigned FULL = 0xffffffffu;
    bool hi16 = (lane & 16) != 0;
    float s0 = hi16 ? p0 : p2;
    float s1 = hi16 ? p1 : p3;
    float r0 = __shfl_xor_sync(FULL, s0, 16);
    float r1 = __shfl_xor_sync(FULL, s1, 16);
    float a0 = (hi16 ? p2 : p0) + r0;
    float a1 = (hi16 ? p3 : p1) + r1;
    bool hi8 = (lane & 8) != 0;
    float s = hi8 ? a0 : a1;
    float r = __shfl_xor_sync(FULL, s, 8);
    float acc = (hi8 ? a1 : a0) + r;
    acc += __shfl_xor_sync(FULL, acc, 4);
    acc += __shfl_xor_sync(FULL, acc, 2);
    acc += __shfl_xor_sync(FULL, acc, 1);
    return acc;
}

__device__ __forceinline__ float dot4(float4 v, float4 q)
{
    float p = v.x * q.x;
    p = fmaf(v.y, q.y, p);
    p = fmaf(v.z, q.z, p);
    p = fmaf(v.w, q.w, p);
    return p;
}

__global__ __launch_bounds__(256, 4)
void attention_max_kernel(const float* __restrict__ q,
                          const float* __restrict__ sub,
                          float* __restrict__ out,
                          int bz)
{
    const int tid  = threadIdx.x;
    const int warp = tid >> 5;        // 0..7, each warp owns 32 support rows
    const int lane = tid & 31;
    const int myrow = (lane >> 3) & 3;
    const unsigned FULL = 0xffffffffu;

    __shared__ float wval[2][8];
    __shared__ int   widx[2][8];

    int parity = 0;

    for (int b = blockIdx.x; b < bz; b += gridDim.x, parity ^= 1) {
        const float4 qc =
            reinterpret_cast<const float4*>(q + (size_t)b * D)[lane];

        const float4* base = reinterpret_cast<const float4*>(
            sub + ((size_t)b * NS + warp * 32) * D);

        float bestv = -CUDART_INF_F;
        int   besti = 0;

        float4 va[4], vb[4];
#pragma unroll
        for (int j = 0; j < 4; ++j)
            va[j] = __ldcs(&base[j * 32 + lane]);

#pragma unroll
        for (int rr = 0; rr < 32; rr += 8) {
#pragma unroll
            for (int j = 0; j < 4; ++j)
                vb[j] = __ldcs(&base[(rr + 4 + j) * 32 + lane]);

            {
                float s = reduce4(dot4(va[0], qc), dot4(va[1], qc),
                                  dot4(va[2], qc), dot4(va[3], qc), lane);
                if (s > bestv) { bestv = s; besti = warp * 32 + rr + myrow; }
            }

            if (rr + 8 < 32) {
#pragma unroll
                for (int j = 0; j < 4; ++j)
                    va[j] = __ldcs(&base[(rr + 8 + j) * 32 + lane]);
            }

            {
                float s = reduce4(dot4(vb[0], qc), dot4(vb[1], qc),
                                  dot4(vb[2], qc), dot4(vb[3], qc), lane);
                if (s > bestv) { bestv = s; besti = warp * 32 + rr + 4 + myrow; }
            }
        }

        // Cross-lane argmax (value max, smaller index wins ties).
#pragma unroll
        for (int m = 16; m > 0; m >>= 1) {
            float ov = __shfl_xor_sync(FULL, bestv, m);
            int   oi = __shfl_xor_sync(FULL, besti, m);
            if (ov > bestv || (ov == bestv && oi < besti)) {
                bestv = ov; besti = oi;
            }
        }

        if (lane == 0) { wval[parity][warp] = bestv; widx[parity][warp] = besti; }
        __syncthreads();   // also protects parity buffer from previous batch

        float bv = wval[parity][0];
        int   bi = widx[parity][0];
#pragma unroll
        for (int w = 1; w < 8; ++w)
            if (wval[parity][w] > bv) { bv = wval[parity][w]; bi = widx[parity][w]; }

        out[(size_t)b * NS + tid] = (tid == bi) ? 1.0f : 0.0f;
    }
}

extern "C" void kernel_launch(void* const* d_in, const int* in_sizes, int n_in,
                              void* d_out, int out_size)
{
    const float* q   = (const float*)d_in[0];   // [4096, 128]
    const float* sub = (const float*)d_in[1];   // [4096, 256, 128]
    float*       out = (float*)d_out;           // [4096, 256, 1]

    const int bz = in_sizes[0] / D;             // 4096

    const int grid = 148 * 4;                   // persistent: 4 CTAs/SM
    attention_max_kernel<<<grid, NS>>>(q, sub, out, bz);
}